// round 9
// baseline (speedup 1.0000x reference)
#include <cuda_runtime.h>
#include <cuda_fp16.h>

#define N_NODES 200000
#define N_EDGES 6400000
#define F_IN 20
#define F_OUT 10
#define XP_STRIDE 12
#define BN_EPS 1e-5f

#define NPB 256                 // nodes per dst bucket
#define NB  782                 // ceil(200000/256)
#define CAP 9216                // bucket capacity (mean 8192 + ~11 sigma)

// ---------------- device scratch ----------------
__device__ float g_sum[F_IN];
__device__ float g_sq[F_IN];
__device__ float g_wsum;
__device__ float g_ad[N_NODES];

struct __align__(32) SrcPack { float4 a; float4 b; };   // 10xfp16 xp + fp32 a_s in ONE sector
__device__ SrcPack g_sx[N_NODES];

__device__ float g_as_self[N_NODES];
__device__ __align__(16) float g_xp[(size_t)N_NODES * XP_STRIDE];
__device__ float4 g_acc[(size_t)N_NODES * 3];           // written whole by aggregate

struct __align__(32) Cursor { int c; int pad[7]; };     // 32B stride: no sector sharing
__device__ Cursor g_cursor[NB];
__device__ uint2 g_staged[(size_t)NB * CAP];            // (src, d_local<<16 | half(w))

__device__ __forceinline__ unsigned pk2(float a, float b) {
    __half2 h = __floats2half2_rn(a, b);
    return *reinterpret_cast<unsigned*>(&h);
}
__device__ __forceinline__ float2 up2(float fbits) {
    unsigned u = __float_as_uint(fbits);
    __half2 h = *reinterpret_cast<__half2*>(&u);
    return __half22float2(h);
}

// ---------------- kernel 0: zero cursors + scalars ----------------
__global__ void k_zero() {
    int i = blockIdx.x * blockDim.x + threadIdx.x;
    if (i < NB) g_cursor[i].c = 0;
    if (i < F_IN) { g_sum[i] = 0.f; g_sq[i] = 0.f; }
    if (i == NB) g_wsum = 0.f;
}

// ---------------- kernel 1: BN batch statistics ----------------
__global__ void k_bn_stats(const float* __restrict__ h) {
    __shared__ float red[8][2 * F_IN];
    int i = blockIdx.x * blockDim.x + threadIdx.x;
    int lane = threadIdx.x & 31;
    int warp = threadIdx.x >> 5;

    float v[F_IN];
#pragma unroll
    for (int f = 0; f < F_IN; f++) v[f] = 0.f;
    if (i < N_NODES) {
#pragma unroll
        for (int f = 0; f < F_IN; f++) v[f] = h[(size_t)i * F_IN + f];
    }
#pragma unroll
    for (int f = 0; f < F_IN; f++) {
        float sv = v[f];
        float qv = v[f] * v[f];
#pragma unroll
        for (int o = 16; o > 0; o >>= 1) {
            sv += __shfl_down_sync(0xffffffffu, sv, o);
            qv += __shfl_down_sync(0xffffffffu, qv, o);
        }
        if (lane == 0) { red[warp][f] = sv; red[warp][F_IN + f] = qv; }
    }
    __syncthreads();
    int j = threadIdx.x;
    if (j < 2 * F_IN) {
        float t = 0.f;
#pragma unroll
        for (int w = 0; w < 8; w++) t += red[w][j];
        if (j < F_IN) atomicAdd(&g_sum[j], t);
        else          atomicAdd(&g_sq[j - F_IN], t);
    }
}

// ---------------- kernel 2: BN + projection + attention terms ----------------
__global__ void k_node_pre(const float* __restrict__ h,
                           const float* __restrict__ bn_w, const float* __restrict__ bn_b,
                           const float* __restrict__ W,
                           const float* __restrict__ att_src, const float* __restrict__ att_dst) {
    __shared__ float s_mu[F_IN], s_rs[F_IN], s_bw[F_IN], s_bb[F_IN];
    __shared__ float s_W[F_OUT * F_IN], s_as[F_OUT], s_ad[F_OUT];
    int t = threadIdx.x;
    if (t < F_IN) {
        float mu = g_sum[t] * (1.f / N_NODES);
        float var = g_sq[t] * (1.f / N_NODES) - mu * mu;
        s_mu[t] = mu;
        s_rs[t] = rsqrtf(var + BN_EPS);
        s_bw[t] = bn_w[t];
        s_bb[t] = bn_b[t];
    }
    if (t < F_OUT) { s_as[t] = att_src[t]; s_ad[t] = att_dst[t]; }
    for (int k = t; k < F_OUT * F_IN; k += blockDim.x) s_W[k] = W[k];
    __syncthreads();

    int i = blockIdx.x * blockDim.x + t;
    if (i >= N_NODES) return;

    float xn[F_IN];
#pragma unroll
    for (int f = 0; f < F_IN; f++)
        xn[f] = (h[(size_t)i * F_IN + f] - s_mu[f]) * s_rs[f] * s_bw[f] + s_bb[f];

    float as = 0.f, ad = 0.f;
    float a[F_OUT];
    float* xr = g_xp + (size_t)i * XP_STRIDE;
#pragma unroll
    for (int o = 0; o < F_OUT; o++) {
        float acc = 0.f;
#pragma unroll
        for (int k = 0; k < F_IN; k++) acc += xn[k] * s_W[o * F_IN + k];
        a[o] = acc;
        xr[o] = acc;
        as += acc * s_as[o];
        ad += acc * s_ad[o];
    }
    g_as_self[i] = as;
    g_ad[i] = ad;

    SrcPack p;
    p.a.x = __uint_as_float(pk2(a[0], a[1]));
    p.a.y = __uint_as_float(pk2(a[2], a[3]));
    p.a.z = __uint_as_float(pk2(a[4], a[5]));
    p.a.w = __uint_as_float(pk2(a[6], a[7]));
    p.b.x = __uint_as_float(pk2(a[8], a[9]));
    p.b.y = as;
    p.b.z = 0.f;
    p.b.w = 0.f;
    g_sx[i] = p;
}

// ---------------- kernel 3a: scatter edges into dst buckets ----------------
__global__ void k_scatter(const int* __restrict__ ei, const float* __restrict__ ew) {
    __shared__ float s_w[8];
    float wacc = 0.f;
    int stride = gridDim.x * blockDim.x;
#pragma unroll 4
    for (int e = blockIdx.x * blockDim.x + threadIdx.x; e < N_EDGES; e += stride) {
        int s = ei[e];
        int d = ei[N_EDGES + e];
        float w = ew[e];
        wacc += w;
        int b  = d >> 8;
        int dl = d & 255;
        int pos = atomicAdd(&g_cursor[b].c, 1);
        if (pos < CAP) {
            unsigned hw = (unsigned)__half_as_ushort(__float2half_rn(w));
            g_staged[(size_t)b * CAP + pos] =
                make_uint2((unsigned)s, ((unsigned)dl << 16) | hw);
        }
    }
#pragma unroll
    for (int o = 16; o > 0; o >>= 1) wacc += __shfl_down_sync(0xffffffffu, wacc, o);
    if ((threadIdx.x & 31) == 0) s_w[threadIdx.x >> 5] = wacc;
    __syncthreads();
    if (threadIdx.x == 0) {
        float t = 0.f;
#pragma unroll
        for (int w = 0; w < 8; w++) t += s_w[w];
        atomicAdd(&g_wsum, t);
    }
}

// ---------------- kernel 3b: per-bucket aggregation in shared memory ----------------
__global__ void __launch_bounds__(NPB) k_aggregate(const float* __restrict__ W_edge,
                                                   const float* __restrict__ att_edge) {
    __shared__ float acc[NPB * 12];     // 11 used + 1 pad per node
    __shared__ float s_adv[NPB];
    int b = blockIdx.x;
    int t = threadIdx.x;

#pragma unroll
    for (int k = t; k < NPB * 12; k += NPB) acc[k] = 0.f;
    int node = b * NPB + t;
    s_adv[t] = (node < N_NODES) ? g_ad[node] : 0.f;

    float c = 0.f;
#pragma unroll
    for (int f = 0; f < F_OUT; f++) c += W_edge[f] * att_edge[f];
    __syncthreads();

    int cnt = g_cursor[b].c;
    if (cnt > CAP) cnt = CAP;
    const uint2* stg = &g_staged[(size_t)b * CAP];
    for (int i = t; i < cnt; i += NPB) {
        uint2 en = stg[i];
        int s  = (int)en.x;
        int dl = (int)(en.y >> 16);
        float w = __half2float(__ushort_as_half((unsigned short)(en.y & 0xffffu)));

        float4 p0 = g_sx[s].a;
        float4 p1 = g_sx[s].b;

        float l = p1.y + s_adv[dl] + c * w;
        l = fmaxf(l, 0.2f * l);
        float ex = __expf(l);

        float2 x01 = up2(p0.x);
        float2 x23 = up2(p0.y);
        float2 x45 = up2(p0.z);
        float2 x67 = up2(p0.w);
        float2 x89 = up2(p1.x);

        float* a = &acc[dl * 12];
        atomicAdd(&a[0], ex * x01.x);
        atomicAdd(&a[1], ex * x01.y);
        atomicAdd(&a[2], ex * x23.x);
        atomicAdd(&a[3], ex * x23.y);
        atomicAdd(&a[4], ex * x45.x);
        atomicAdd(&a[5], ex * x45.y);
        atomicAdd(&a[6], ex * x67.x);
        atomicAdd(&a[7], ex * x67.y);
        atomicAdd(&a[8], ex * x89.x);
        atomicAdd(&a[9], ex * x89.y);
        atomicAdd(&a[10], ex);
    }
    __syncthreads();

    if (node < N_NODES) {
        const float* a = &acc[t * 12];
        g_acc[(size_t)node * 3 + 0] = make_float4(a[0], a[1], a[2], a[3]);
        g_acc[(size_t)node * 3 + 1] = make_float4(a[4], a[5], a[6], a[7]);
        g_acc[(size_t)node * 3 + 2] = make_float4(a[8], a[9], a[10], 0.f);
    }
}

// ---------------- kernel 4: self-loop + normalize + bias + MLP + outputs ----------------
__global__ void k_node_post(const float* __restrict__ W_edge, const float* __restrict__ att_edge,
                            const float* __restrict__ bias,
                            const float* __restrict__ fc1w, const float* __restrict__ fc1b,
                            const float* __restrict__ fc2w, const float* __restrict__ fc2b,
                            const float* __restrict__ fc3w, const float* __restrict__ fc3b,
                            float* __restrict__ out) {
    __shared__ float s1[F_OUT * F_OUT], s2[F_OUT * F_OUT], s3[F_OUT * F_OUT];
    __shared__ float b1[F_OUT], b2[F_OUT], b3[F_OUT], sb[F_OUT];
    int t = threadIdx.x;
    for (int k = t; k < F_OUT * F_OUT; k += blockDim.x) {
        s1[k] = fc1w[k]; s2[k] = fc2w[k]; s3[k] = fc3w[k];
    }
    if (t < F_OUT) { b1[t] = fc1b[t]; b2[t] = fc2b[t]; b3[t] = fc3b[t]; sb[t] = bias[t]; }
    __syncthreads();

    float c = 0.f;
#pragma unroll
    for (int f = 0; f < F_OUT; f++) c += W_edge[f] * att_edge[f];
    float wbar = g_wsum * (1.f / N_EDGES);

    int i = blockIdx.x * blockDim.x + t;
    if (i >= N_NODES) return;

    float l = g_as_self[i] + g_ad[i] + c * wbar;
    l = fmaxf(l, 0.2f * l);
    float exl = __expf(l);

    const float4* ab = &g_acc[(size_t)i * 3];
    float4 A0 = ab[0], A1 = ab[1], A2 = ab[2];
    const float* xr = g_xp + (size_t)i * XP_STRIDE;

    float num[F_OUT];
    num[0] = A0.x; num[1] = A0.y; num[2] = A0.z; num[3] = A0.w;
    num[4] = A1.x; num[5] = A1.y; num[6] = A1.z; num[7] = A1.w;
    num[8] = A2.x; num[9] = A2.y;
    float den = A2.z + exl;
    float rden = 1.f / den;

    float o[F_OUT];
#pragma unroll
    for (int f = 0; f < F_OUT; f++)
        o[f] = (num[f] + exl * xr[f]) * rden + sb[f];

    float* emb = out + (size_t)i * F_OUT;
#pragma unroll
    for (int f = 0; f < F_OUT; f++) emb[f] = fmaxf(o[f], 0.f);

    float y1[F_OUT], y2[F_OUT];
#pragma unroll
    for (int f = 0; f < F_OUT; f++) {
        float acc = b1[f];
#pragma unroll
        for (int k = 0; k < F_OUT; k++) acc += o[k] * s1[f * F_OUT + k];
        y1[f] = fmaxf(acc, 0.f);
    }
#pragma unroll
    for (int f = 0; f < F_OUT; f++) {
        float acc = b2[f];
#pragma unroll
        for (int k = 0; k < F_OUT; k++) acc += y1[k] * s2[f * F_OUT + k];
        y2[f] = fmaxf(acc, 0.f);
    }
    float* yo = out + (size_t)N_NODES * F_OUT + (size_t)i * F_OUT;
#pragma unroll
    for (int f = 0; f < F_OUT; f++) {
        float acc = b3[f];
#pragma unroll
        for (int k = 0; k < F_OUT; k++) acc += y2[k] * s3[f * F_OUT + k];
        yo[f] = acc;
    }
}

// ---------------- launch ----------------
extern "C" void kernel_launch(void* const* d_in, const int* in_sizes, int n_in,
                              void* d_out, int out_size) {
    const float* h        = (const float*)d_in[0];
    const int*   ei       = (const int*)d_in[1];
    const float* ew       = (const float*)d_in[2];
    const float* bn_w     = (const float*)d_in[3];
    const float* bn_b     = (const float*)d_in[4];
    const float* W        = (const float*)d_in[5];
    const float* att_src  = (const float*)d_in[6];
    const float* att_dst  = (const float*)d_in[7];
    const float* att_edge = (const float*)d_in[8];
    const float* W_edge   = (const float*)d_in[9];
    const float* bias     = (const float*)d_in[10];
    const float* fc1w     = (const float*)d_in[11];
    const float* fc1b     = (const float*)d_in[12];
    const float* fc2w     = (const float*)d_in[13];
    const float* fc2b     = (const float*)d_in[14];
    const float* fc3w     = (const float*)d_in[15];
    const float* fc3b     = (const float*)d_in[16];
    float* out = (float*)d_out;

    const int TPB = 256;
    const int node_blocks = (N_NODES + TPB - 1) / TPB;

    k_zero<<<(NB + TPB) / TPB + 1, TPB>>>();
    k_scatter<<<1184, TPB>>>(ei, ew);
    k_bn_stats<<<node_blocks, TPB>>>(h);
    k_node_pre<<<node_blocks, TPB>>>(h, bn_w, bn_b, W, att_src, att_dst);
    k_aggregate<<<NB, NPB>>>(W_edge, att_edge);
    k_node_post<<<node_blocks, TPB>>>(W_edge, att_edge, bias,
                                      fc1w, fc1b, fc2w, fc2b, fc3w, fc3b, out);
}

// round 10
// speedup vs baseline: 1.3206x; 1.3206x over previous
#include <cuda_runtime.h>
#include <cuda_fp16.h>

#define N_NODES 200000
#define N_EDGES 6400000
#define F_IN 20
#define F_OUT 10
#define XP_STRIDE 12
#define BN_EPS 1e-5f

#define NPB 256                 // nodes per dst bucket
#define NB  782                 // ceil(200000/256)
#define CAP 9216                // bucket capacity (mean 8192 + ~11 sigma)
#define SCAT_BLOCKS 592
#define SPAN ((N_EDGES + SCAT_BLOCKS - 1) / SCAT_BLOCKS)   // 10811

// ---------------- device scratch ----------------
__device__ float g_sum[F_IN];
__device__ float g_sq[F_IN];
__device__ float g_wsum;
__device__ float g_ad[N_NODES];

struct __align__(32) SrcPack { float4 a; float4 b; };   // 10xfp16 xp + fp32 a_s in ONE sector
__device__ SrcPack g_sx[N_NODES];

__device__ float g_as_self[N_NODES];
__device__ __align__(16) float g_xp[(size_t)N_NODES * XP_STRIDE];
__device__ float4 g_acc[(size_t)N_NODES * 3];           // written whole by aggregate

struct __align__(32) Cursor { int c; int pad[7]; };     // 32B stride: no sector sharing
__device__ Cursor g_cursor[NB];
__device__ uint2 g_staged[(size_t)NB * CAP];            // (src, d_local<<16 | half(w))

__device__ __forceinline__ unsigned pk2(float a, float b) {
    __half2 h = __floats2half2_rn(a, b);
    return *reinterpret_cast<unsigned*>(&h);
}
__device__ __forceinline__ float2 up2(float fbits) {
    unsigned u = __float_as_uint(fbits);
    __half2 h = *reinterpret_cast<__half2*>(&u);
    return __half22float2(h);
}

// ---------------- kernel 0: zero cursors + scalars ----------------
__global__ void k_zero() {
    int i = blockIdx.x * blockDim.x + threadIdx.x;
    if (i < NB) g_cursor[i].c = 0;
    if (i < F_IN) { g_sum[i] = 0.f; g_sq[i] = 0.f; }
    if (i == NB) g_wsum = 0.f;
}

// ---------------- kernel 1: BN batch statistics ----------------
__global__ void k_bn_stats(const float* __restrict__ h) {
    __shared__ float red[8][2 * F_IN];
    int i = blockIdx.x * blockDim.x + threadIdx.x;
    int lane = threadIdx.x & 31;
    int warp = threadIdx.x >> 5;

    float v[F_IN];
#pragma unroll
    for (int f = 0; f < F_IN; f++) v[f] = 0.f;
    if (i < N_NODES) {
#pragma unroll
        for (int f = 0; f < F_IN; f++) v[f] = h[(size_t)i * F_IN + f];
    }
#pragma unroll
    for (int f = 0; f < F_IN; f++) {
        float sv = v[f];
        float qv = v[f] * v[f];
#pragma unroll
        for (int o = 16; o > 0; o >>= 1) {
            sv += __shfl_down_sync(0xffffffffu, sv, o);
            qv += __shfl_down_sync(0xffffffffu, qv, o);
        }
        if (lane == 0) { red[warp][f] = sv; red[warp][F_IN + f] = qv; }
    }
    __syncthreads();
    int j = threadIdx.x;
    if (j < 2 * F_IN) {
        float t = 0.f;
#pragma unroll
        for (int w = 0; w < 8; w++) t += red[w][j];
        if (j < F_IN) atomicAdd(&g_sum[j], t);
        else          atomicAdd(&g_sq[j - F_IN], t);
    }
}

// ---------------- kernel 2: BN + projection + attention terms ----------------
__global__ void k_node_pre(const float* __restrict__ h,
                           const float* __restrict__ bn_w, const float* __restrict__ bn_b,
                           const float* __restrict__ W,
                           const float* __restrict__ att_src, const float* __restrict__ att_dst) {
    __shared__ float s_mu[F_IN], s_rs[F_IN], s_bw[F_IN], s_bb[F_IN];
    __shared__ float s_W[F_OUT * F_IN], s_as[F_OUT], s_ad[F_OUT];
    int t = threadIdx.x;
    if (t < F_IN) {
        float mu = g_sum[t] * (1.f / N_NODES);
        float var = g_sq[t] * (1.f / N_NODES) - mu * mu;
        s_mu[t] = mu;
        s_rs[t] = rsqrtf(var + BN_EPS);
        s_bw[t] = bn_w[t];
        s_bb[t] = bn_b[t];
    }
    if (t < F_OUT) { s_as[t] = att_src[t]; s_ad[t] = att_dst[t]; }
    for (int k = t; k < F_OUT * F_IN; k += blockDim.x) s_W[k] = W[k];
    __syncthreads();

    int i = blockIdx.x * blockDim.x + t;
    if (i >= N_NODES) return;

    float xn[F_IN];
#pragma unroll
    for (int f = 0; f < F_IN; f++)
        xn[f] = (h[(size_t)i * F_IN + f] - s_mu[f]) * s_rs[f] * s_bw[f] + s_bb[f];

    float as = 0.f, ad = 0.f;
    float a[F_OUT];
    float* xr = g_xp + (size_t)i * XP_STRIDE;
#pragma unroll
    for (int o = 0; o < F_OUT; o++) {
        float acc = 0.f;
#pragma unroll
        for (int k = 0; k < F_IN; k++) acc += xn[k] * s_W[o * F_IN + k];
        a[o] = acc;
        xr[o] = acc;
        as += acc * s_as[o];
        ad += acc * s_ad[o];
    }
    g_as_self[i] = as;
    g_ad[i] = ad;

    SrcPack p;
    p.a.x = __uint_as_float(pk2(a[0], a[1]));
    p.a.y = __uint_as_float(pk2(a[2], a[3]));
    p.a.z = __uint_as_float(pk2(a[4], a[5]));
    p.a.w = __uint_as_float(pk2(a[6], a[7]));
    p.b.x = __uint_as_float(pk2(a[8], a[9]));
    p.b.y = as;
    p.b.z = 0.f;
    p.b.w = 0.f;
    g_sx[i] = p;
}

// ---------------- kernel 3a: scatter with hierarchical claiming ----------------
__global__ void __launch_bounds__(256) k_scatter(const int* __restrict__ ei,
                                                 const float* __restrict__ ew) {
    __shared__ int cnt[NB];
    __shared__ int base[NB];
    __shared__ float s_w[8];
    int t = threadIdx.x;

    for (int b = t; b < NB; b += 256) cnt[b] = 0;
    __syncthreads();

    int e0 = blockIdx.x * SPAN;
    int e1 = e0 + SPAN;
    if (e1 > N_EDGES) e1 = N_EDGES;

    // Phase 1: count bucket occupancy (smem, spread atomics) + edge-weight sum
    float wacc = 0.f;
    for (int e = e0 + t; e < e1; e += 256) {
        int d = ei[N_EDGES + e];
        atomicAdd(&cnt[d >> 8], 1);
        wacc += ew[e];
    }
    __syncthreads();

    // Phase 2: one global claim per (block, bucket)
    for (int b = t; b < NB; b += 256) {
        int c = cnt[b];
        base[b] = c ? atomicAdd(&g_cursor[b].c, c) : 0;
        cnt[b] = 0;
    }
    __syncthreads();

    // Phase 3: write staged entries into reserved, mostly-contiguous slots
    for (int e = e0 + t; e < e1; e += 256) {
        int s = ei[e];
        int d = ei[N_EDGES + e];
        float w = ew[e];
        int b  = d >> 8;
        int dl = d & 255;
        int pos = base[b] + atomicAdd(&cnt[b], 1);
        if (pos < CAP) {
            unsigned hw = (unsigned)__half_as_ushort(__float2half_rn(w));
            g_staged[(size_t)b * CAP + pos] =
                make_uint2((unsigned)s, ((unsigned)dl << 16) | hw);
        }
    }

#pragma unroll
    for (int o = 16; o > 0; o >>= 1) wacc += __shfl_down_sync(0xffffffffu, wacc, o);
    if ((t & 31) == 0) s_w[t >> 5] = wacc;
    __syncthreads();
    if (t == 0) {
        float tt = 0.f;
#pragma unroll
        for (int w = 0; w < 8; w++) tt += s_w[w];
        atomicAdd(&g_wsum, tt);
    }
}

// ---------------- kernel 3b: per-bucket aggregation in shared memory ----------------
__global__ void __launch_bounds__(NPB) k_aggregate(const float* __restrict__ W_edge,
                                                   const float* __restrict__ att_edge) {
    __shared__ float acc[NPB * 12];     // 11 used + 1 pad per node
    __shared__ float s_adv[NPB];
    int b = blockIdx.x;
    int t = threadIdx.x;

#pragma unroll
    for (int k = t; k < NPB * 12; k += NPB) acc[k] = 0.f;
    int node = b * NPB + t;
    s_adv[t] = (node < N_NODES) ? g_ad[node] : 0.f;

    float c = 0.f;
#pragma unroll
    for (int f = 0; f < F_OUT; f++) c += W_edge[f] * att_edge[f];
    __syncthreads();

    int cnt = g_cursor[b].c;
    if (cnt > CAP) cnt = CAP;
    const uint2* stg = &g_staged[(size_t)b * CAP];
    for (int i = t; i < cnt; i += NPB) {
        uint2 en = stg[i];
        int s  = (int)en.x;
        int dl = (int)(en.y >> 16);
        float w = __half2float(__ushort_as_half((unsigned short)(en.y & 0xffffu)));

        float4 p0 = g_sx[s].a;
        float4 p1 = g_sx[s].b;

        float l = p1.y + s_adv[dl] + c * w;
        l = fmaxf(l, 0.2f * l);
        float ex = __expf(l);

        float2 x01 = up2(p0.x);
        float2 x23 = up2(p0.y);
        float2 x45 = up2(p0.z);
        float2 x67 = up2(p0.w);
        float2 x89 = up2(p1.x);

        float* a = &acc[dl * 12];
        atomicAdd(&a[0], ex * x01.x);
        atomicAdd(&a[1], ex * x01.y);
        atomicAdd(&a[2], ex * x23.x);
        atomicAdd(&a[3], ex * x23.y);
        atomicAdd(&a[4], ex * x45.x);
        atomicAdd(&a[5], ex * x45.y);
        atomicAdd(&a[6], ex * x67.x);
        atomicAdd(&a[7], ex * x67.y);
        atomicAdd(&a[8], ex * x89.x);
        atomicAdd(&a[9], ex * x89.y);
        atomicAdd(&a[10], ex);
    }
    __syncthreads();

    if (node < N_NODES) {
        const float* a = &acc[t * 12];
        g_acc[(size_t)node * 3 + 0] = make_float4(a[0], a[1], a[2], a[3]);
        g_acc[(size_t)node * 3 + 1] = make_float4(a[4], a[5], a[6], a[7]);
        g_acc[(size_t)node * 3 + 2] = make_float4(a[8], a[9], a[10], 0.f);
    }
}

// ---------------- kernel 4: self-loop + normalize + bias + MLP + outputs ----------------
__global__ void k_node_post(const float* __restrict__ W_edge, const float* __restrict__ att_edge,
                            const float* __restrict__ bias,
                            const float* __restrict__ fc1w, const float* __restrict__ fc1b,
                            const float* __restrict__ fc2w, const float* __restrict__ fc2b,
                            const float* __restrict__ fc3w, const float* __restrict__ fc3b,
                            float* __restrict__ out) {
    __shared__ float s1[F_OUT * F_OUT], s2[F_OUT * F_OUT], s3[F_OUT * F_OUT];
    __shared__ float b1[F_OUT], b2[F_OUT], b3[F_OUT], sb[F_OUT];
    int t = threadIdx.x;
    for (int k = t; k < F_OUT * F_OUT; k += blockDim.x) {
        s1[k] = fc1w[k]; s2[k] = fc2w[k]; s3[k] = fc3w[k];
    }
    if (t < F_OUT) { b1[t] = fc1b[t]; b2[t] = fc2b[t]; b3[t] = fc3b[t]; sb[t] = bias[t]; }
    __syncthreads();

    float c = 0.f;
#pragma unroll
    for (int f = 0; f < F_OUT; f++) c += W_edge[f] * att_edge[f];
    float wbar = g_wsum * (1.f / N_EDGES);

    int i = blockIdx.x * blockDim.x + t;
    if (i >= N_NODES) return;

    float l = g_as_self[i] + g_ad[i] + c * wbar;
    l = fmaxf(l, 0.2f * l);
    float exl = __expf(l);

    const float4* ab = &g_acc[(size_t)i * 3];
    float4 A0 = ab[0], A1 = ab[1], A2 = ab[2];
    const float* xr = g_xp + (size_t)i * XP_STRIDE;

    float num[F_OUT];
    num[0] = A0.x; num[1] = A0.y; num[2] = A0.z; num[3] = A0.w;
    num[4] = A1.x; num[5] = A1.y; num[6] = A1.z; num[7] = A1.w;
    num[8] = A2.x; num[9] = A2.y;
    float den = A2.z + exl;
    float rden = 1.f / den;

    float o[F_OUT];
#pragma unroll
    for (int f = 0; f < F_OUT; f++)
        o[f] = (num[f] + exl * xr[f]) * rden + sb[f];

    float* emb = out + (size_t)i * F_OUT;
#pragma unroll
    for (int f = 0; f < F_OUT; f++) emb[f] = fmaxf(o[f], 0.f);

    float y1[F_OUT], y2[F_OUT];
#pragma unroll
    for (int f = 0; f < F_OUT; f++) {
        float acc = b1[f];
#pragma unroll
        for (int k = 0; k < F_OUT; k++) acc += o[k] * s1[f * F_OUT + k];
        y1[f] = fmaxf(acc, 0.f);
    }
#pragma unroll
    for (int f = 0; f < F_OUT; f++) {
        float acc = b2[f];
#pragma unroll
        for (int k = 0; k < F_OUT; k++) acc += y1[k] * s2[f * F_OUT + k];
        y2[f] = fmaxf(acc, 0.f);
    }
    float* yo = out + (size_t)N_NODES * F_OUT + (size_t)i * F_OUT;
#pragma unroll
    for (int f = 0; f < F_OUT; f++) {
        float acc = b3[f];
#pragma unroll
        for (int k = 0; k < F_OUT; k++) acc += y2[k] * s3[f * F_OUT + k];
        yo[f] = acc;
    }
}

// ---------------- launch ----------------
extern "C" void kernel_launch(void* const* d_in, const int* in_sizes, int n_in,
                              void* d_out, int out_size) {
    const float* h        = (const float*)d_in[0];
    const int*   ei       = (const int*)d_in[1];
    const float* ew       = (const float*)d_in[2];
    const float* bn_w     = (const float*)d_in[3];
    const float* bn_b     = (const float*)d_in[4];
    const float* W        = (const float*)d_in[5];
    const float* att_src  = (const float*)d_in[6];
    const float* att_dst  = (const float*)d_in[7];
    const float* att_edge = (const float*)d_in[8];
    const float* W_edge   = (const float*)d_in[9];
    const float* bias     = (const float*)d_in[10];
    const float* fc1w     = (const float*)d_in[11];
    const float* fc1b     = (const float*)d_in[12];
    const float* fc2w     = (const float*)d_in[13];
    const float* fc2b     = (const float*)d_in[14];
    const float* fc3w     = (const float*)d_in[15];
    const float* fc3b     = (const float*)d_in[16];
    float* out = (float*)d_out;

    const int TPB = 256;
    const int node_blocks = (N_NODES + TPB - 1) / TPB;

    k_zero<<<4, TPB>>>();
    k_scatter<<<SCAT_BLOCKS, TPB>>>(ei, ew);
    k_bn_stats<<<node_blocks, TPB>>>(h);
    k_node_pre<<<node_blocks, TPB>>>(h, bn_w, bn_b, W, att_src, att_dst);
    k_aggregate<<<NB, NPB>>>(W_edge, att_edge);
    k_node_post<<<node_blocks, TPB>>>(W_edge, att_edge, bias,
                                      fc1w, fc1b, fc2w, fc2b, fc3w, fc3b, out);
}

// round 12
// speedup vs baseline: 2.6976x; 2.0427x over previous
#include <cuda_runtime.h>
#include <cuda_fp16.h>

#define N_NODES 200000
#define N_EDGES 6400000
#define EHALF   (N_EDGES / 2)
#define F_IN 20
#define F_OUT 10
#define XP_STRIDE 12
#define BN_EPS 1e-5f

// ---------------- device scratch ----------------
__device__ float g_sum[F_IN];
__device__ float g_sq[F_IN];
__device__ float g_wsum;
__device__ float g_ad[N_NODES];

struct __align__(32) SrcPack { float4 a; float4 b; };   // 10xfp16 xp + fp32 a_s in ONE 32B sector
__device__ SrcPack g_sx[N_NODES];

__device__ float g_as_self[N_NODES];
__device__ __align__(16) float g_xp[(size_t)N_NODES * XP_STRIDE];
__device__ float4 g_acc[(size_t)N_NODES * 3];           // [num0..3][num4..7][num8,num9,den,-]

__device__ __forceinline__ void red_add_v4(float4* addr, float a, float b, float c, float d) {
    asm volatile("red.global.add.v4.f32 [%0], {%1, %2, %3, %4};"
                 :: "l"(addr), "f"(a), "f"(b), "f"(c), "f"(d)
                 : "memory");
}

__device__ __forceinline__ unsigned pk2(float a, float b) {
    __half2 h = __floats2half2_rn(a, b);
    return *reinterpret_cast<unsigned*>(&h);
}
__device__ __forceinline__ float2 up2(float fbits) {
    unsigned u = __float_as_uint(fbits);
    __half2 h = *reinterpret_cast<__half2*>(&u);
    return __half22float2(h);
}

// ---------------- kernel 0: zero accumulators ----------------
__global__ void k_zero() {
    size_t stride = (size_t)gridDim.x * blockDim.x;
    size_t total = (size_t)N_NODES * 3;
    for (size_t i = (size_t)blockIdx.x * blockDim.x + threadIdx.x; i < total; i += stride)
        g_acc[i] = make_float4(0.f, 0.f, 0.f, 0.f);
    if (blockIdx.x == 0) {
        if (threadIdx.x < F_IN) { g_sum[threadIdx.x] = 0.f; g_sq[threadIdx.x] = 0.f; }
        if (threadIdx.x == 32) g_wsum = 0.f;
    }
}

// ---------------- kernel 1: BN batch statistics ----------------
__global__ void k_bn_stats(const float* __restrict__ h) {
    __shared__ float red[8][2 * F_IN];
    int i = blockIdx.x * blockDim.x + threadIdx.x;
    int lane = threadIdx.x & 31;
    int warp = threadIdx.x >> 5;

    float v[F_IN];
#pragma unroll
    for (int f = 0; f < F_IN; f++) v[f] = 0.f;
    if (i < N_NODES) {
#pragma unroll
        for (int f = 0; f < F_IN; f++) v[f] = h[(size_t)i * F_IN + f];
    }
#pragma unroll
    for (int f = 0; f < F_IN; f++) {
        float sv = v[f];
        float qv = v[f] * v[f];
#pragma unroll
        for (int o = 16; o > 0; o >>= 1) {
            sv += __shfl_down_sync(0xffffffffu, sv, o);
            qv += __shfl_down_sync(0xffffffffu, qv, o);
        }
        if (lane == 0) { red[warp][f] = sv; red[warp][F_IN + f] = qv; }
    }
    __syncthreads();
    int j = threadIdx.x;
    if (j < 2 * F_IN) {
        float t = 0.f;
#pragma unroll
        for (int w = 0; w < 8; w++) t += red[w][j];
        if (j < F_IN) atomicAdd(&g_sum[j], t);
        else          atomicAdd(&g_sq[j - F_IN], t);
    }
}

// ---------------- kernel 2: BN + projection + attention terms ----------------
__global__ void k_node_pre(const float* __restrict__ h,
                           const float* __restrict__ bn_w, const float* __restrict__ bn_b,
                           const float* __restrict__ W,
                           const float* __restrict__ att_src, const float* __restrict__ att_dst) {
    __shared__ float s_mu[F_IN], s_rs[F_IN], s_bw[F_IN], s_bb[F_IN];
    __shared__ float s_W[F_OUT * F_IN], s_as[F_OUT], s_ad[F_OUT];
    int t = threadIdx.x;
    if (t < F_IN) {
        float mu = g_sum[t] * (1.f / N_NODES);
        float var = g_sq[t] * (1.f / N_NODES) - mu * mu;
        s_mu[t] = mu;
        s_rs[t] = rsqrtf(var + BN_EPS);
        s_bw[t] = bn_w[t];
        s_bb[t] = bn_b[t];
    }
    if (t < F_OUT) { s_as[t] = att_src[t]; s_ad[t] = att_dst[t]; }
    for (int k = t; k < F_OUT * F_IN; k += blockDim.x) s_W[k] = W[k];
    __syncthreads();

    int i = blockIdx.x * blockDim.x + t;
    if (i >= N_NODES) return;

    float xn[F_IN];
#pragma unroll
    for (int f = 0; f < F_IN; f++)
        xn[f] = (h[(size_t)i * F_IN + f] - s_mu[f]) * s_rs[f] * s_bw[f] + s_bb[f];

    float as = 0.f, ad = 0.f;
    float a[F_OUT];
    float* xr = g_xp + (size_t)i * XP_STRIDE;
#pragma unroll
    for (int o = 0; o < F_OUT; o++) {
        float acc = 0.f;
#pragma unroll
        for (int k = 0; k < F_IN; k++) acc += xn[k] * s_W[o * F_IN + k];
        a[o] = acc;
        xr[o] = acc;
        as += acc * s_as[o];
        ad += acc * s_ad[o];
    }
    g_as_self[i] = as;
    g_ad[i] = ad;

    SrcPack p;
    p.a.x = __uint_as_float(pk2(a[0], a[1]));
    p.a.y = __uint_as_float(pk2(a[2], a[3]));
    p.a.z = __uint_as_float(pk2(a[4], a[5]));
    p.a.w = __uint_as_float(pk2(a[6], a[7]));
    p.b.x = __uint_as_float(pk2(a[8], a[9]));
    p.b.y = as;
    p.b.z = 0.f;
    p.b.w = 0.f;
    g_sx[i] = p;
}

// ---------------- kernel 3: edge pass, dual-edge per iteration for MLP ----------------
__global__ void __launch_bounds__(256) k_edges(const int* __restrict__ ei,
                                               const float* __restrict__ ew,
                                               const float* __restrict__ W_edge,
                                               const float* __restrict__ att_edge) {
    __shared__ float s_w[8];
    float c = 0.f;
#pragma unroll
    for (int f = 0; f < F_OUT; f++) c += W_edge[f] * att_edge[f];

    float wacc = 0.f;
    int stride = gridDim.x * blockDim.x;
    for (int e = blockIdx.x * blockDim.x + threadIdx.x; e < EHALF; e += stride) {
        int e2 = e + EHALF;
        // -- batch all independent loads (streams + 4 random gathers) --
        int   s0 = ei[e];
        int   d0 = ei[N_EDGES + e];
        float w0 = ew[e];
        int   s1 = ei[e2];
        int   d1 = ei[N_EDGES + e2];
        float w1 = ew[e2];

        float4 p0a = g_sx[s0].a;
        float4 p0b = g_sx[s0].b;
        float4 p1a = g_sx[s1].a;
        float4 p1b = g_sx[s1].b;
        float  ad0 = g_ad[d0];
        float  ad1 = g_ad[d1];

        wacc += w0 + w1;

        // -- edge 0 --
        {
            float l = p0b.y + ad0 + c * w0;
            l = fmaxf(l, 0.2f * l);
            float ex = __expf(l);
            float2 x01 = up2(p0a.x);
            float2 x23 = up2(p0a.y);
            float2 x45 = up2(p0a.z);
            float2 x67 = up2(p0a.w);
            float2 x89 = up2(p0b.x);
            float4* ab = &g_acc[(size_t)d0 * 3];
            red_add_v4(&ab[0], ex * x01.x, ex * x01.y, ex * x23.x, ex * x23.y);
            red_add_v4(&ab[1], ex * x45.x, ex * x45.y, ex * x67.x, ex * x67.y);
            red_add_v4(&ab[2], ex * x89.x, ex * x89.y, ex, 0.f);
        }
        // -- edge 1 --
        {
            float l = p1b.y + ad1 + c * w1;
            l = fmaxf(l, 0.2f * l);
            float ex = __expf(l);
            float2 x01 = up2(p1a.x);
            float2 x23 = up2(p1a.y);
            float2 x45 = up2(p1a.z);
            float2 x67 = up2(p1a.w);
            float2 x89 = up2(p1b.x);
            float4* ab = &g_acc[(size_t)d1 * 3];
            red_add_v4(&ab[0], ex * x01.x, ex * x01.y, ex * x23.x, ex * x23.y);
            red_add_v4(&ab[1], ex * x45.x, ex * x45.y, ex * x67.x, ex * x67.y);
            red_add_v4(&ab[2], ex * x89.x, ex * x89.y, ex, 0.f);
        }
    }

#pragma unroll
    for (int o = 16; o > 0; o >>= 1) wacc += __shfl_down_sync(0xffffffffu, wacc, o);
    if ((threadIdx.x & 31) == 0) s_w[threadIdx.x >> 5] = wacc;
    __syncthreads();
    if (threadIdx.x == 0) {
        float t = 0.f;
#pragma unroll
        for (int w = 0; w < 8; w++) t += s_w[w];
        atomicAdd(&g_wsum, t);
    }
}

// ---------------- kernel 4: self-loop + normalize + bias + MLP + outputs ----------------
__global__ void k_node_post(const float* __restrict__ W_edge, const float* __restrict__ att_edge,
                            const float* __restrict__ bias,
                            const float* __restrict__ fc1w, const float* __restrict__ fc1b,
                            const float* __restrict__ fc2w, const float* __restrict__ fc2b,
                            const float* __restrict__ fc3w, const float* __restrict__ fc3b,
                            float* __restrict__ out) {
    __shared__ float s1[F_OUT * F_OUT], s2[F_OUT * F_OUT], s3[F_OUT * F_OUT];
    __shared__ float b1[F_OUT], b2[F_OUT], b3[F_OUT], sb[F_OUT];
    int t = threadIdx.x;
    for (int k = t; k < F_OUT * F_OUT; k += blockDim.x) {
        s1[k] = fc1w[k]; s2[k] = fc2w[k]; s3[k] = fc3w[k];
    }
    if (t < F_OUT) { b1[t] = fc1b[t]; b2[t] = fc2b[t]; b3[t] = fc3b[t]; sb[t] = bias[t]; }
    __syncthreads();

    float c = 0.f;
#pragma unroll
    for (int f = 0; f < F_OUT; f++) c += W_edge[f] * att_edge[f];
    float wbar = g_wsum * (1.f / N_EDGES);

    int i = blockIdx.x * blockDim.x + t;
    if (i >= N_NODES) return;

    float l = g_as_self[i] + g_ad[i] + c * wbar;
    l = fmaxf(l, 0.2f * l);
    float exl = __expf(l);

    const float4* ab = &g_acc[(size_t)i * 3];
    float4 A0 = ab[0], A1 = ab[1], A2 = ab[2];
    const float* xr = g_xp + (size_t)i * XP_STRIDE;

    float num[F_OUT];
    num[0] = A0.x; num[1] = A0.y; num[2] = A0.z; num[3] = A0.w;
    num[4] = A1.x; num[5] = A1.y; num[6] = A1.z; num[7] = A1.w;
    num[8] = A2.x; num[9] = A2.y;
    float den = A2.z + exl;
    float rden = 1.f / den;

    float o[F_OUT];
#pragma unroll
    for (int f = 0; f < F_OUT; f++)
        o[f] = (num[f] + exl * xr[f]) * rden + sb[f];

    float* emb = out + (size_t)i * F_OUT;
#pragma unroll
    for (int f = 0; f < F_OUT; f++) emb[f] = fmaxf(o[f], 0.f);

    float y1[F_OUT], y2[F_OUT];
#pragma unroll
    for (int f = 0; f < F_OUT; f++) {
        float acc = b1[f];
#pragma unroll
        for (int k = 0; k < F_OUT; k++) acc += o[k] * s1[f * F_OUT + k];
        y1[f] = fmaxf(acc, 0.f);
    }
#pragma unroll
    for (int f = 0; f < F_OUT; f++) {
        float acc = b2[f];
#pragma unroll
        for (int k = 0; k < F_OUT; k++) acc += y1[k] * s2[f * F_OUT + k];
        y2[f] = fmaxf(acc, 0.f);
    }
    float* yo = out + (size_t)N_NODES * F_OUT + (size_t)i * F_OUT;
#pragma unroll
    for (int f = 0; f < F_OUT; f++) {
        float acc = b3[f];
#pragma unroll
        for (int k = 0; k < F_OUT; k++) acc += y2[k] * s3[f * F_OUT + k];
        yo[f] = acc;
    }
}

// ---------------- launch ----------------
extern "C" void kernel_launch(void* const* d_in, const int* in_sizes, int n_in,
                              void* d_out, int out_size) {
    const float* h        = (const float*)d_in[0];
    const int*   ei       = (const int*)d_in[1];
    const float* ew       = (const float*)d_in[2];
    const float* bn_w     = (const float*)d_in[3];
    const float* bn_b     = (const float*)d_in[4];
    const float* W        = (const float*)d_in[5];
    const float* att_src  = (const float*)d_in[6];
    const float* att_dst  = (const float*)d_in[7];
    const float* att_edge = (const float*)d_in[8];
    const float* W_edge   = (const float*)d_in[9];
    const float* bias     = (const float*)d_in[10];
    const float* fc1w     = (const float*)d_in[11];
    const float* fc1b     = (const float*)d_in[12];
    const float* fc2w     = (const float*)d_in[13];
    const float* fc2b     = (const float*)d_in[14];
    const float* fc3w     = (const float*)d_in[15];
    const float* fc3b     = (const float*)d_in[16];
    float* out = (float*)d_out;

    const int TPB = 256;
    const int node_blocks = (N_NODES + TPB - 1) / TPB;

    k_zero<<<1184, TPB>>>();
    k_bn_stats<<<node_blocks, TPB>>>(h);
    k_node_pre<<<node_blocks, TPB>>>(h, bn_w, bn_b, W, att_src, att_dst);
    k_edges<<<1184, TPB>>>(ei, ew, W_edge, att_edge);
    k_node_post<<<node_blocks, TPB>>>(W_edge, att_edge, bias,
                                      fc1w, fc1b, fc2w, fc2b, fc3w, fc3b, out);
}

// round 14
// speedup vs baseline: 2.6981x; 1.0002x over previous
#include <cuda_runtime.h>
#include <cuda_fp16.h>

#define N_NODES 200000
#define N_EDGES 6400000
#define EPAIRS  (N_EDGES / 2)
#define F_IN 20
#define F_OUT 10
#define XP_STRIDE 12
#define BN_EPS 1e-5f

// ---------------- device scratch ----------------
__device__ float g_sum[F_IN];
__device__ float g_sq[F_IN];
__device__ float g_wsum;
__device__ float g_ad[N_NODES];

struct __align__(32) SrcPack { float4 a; float4 b; };   // 10xfp16 xp + fp32 a_s in ONE 32B sector
__device__ SrcPack g_sx[N_NODES];

__device__ float g_as_self[N_NODES];
__device__ __align__(16) float g_xp[(size_t)N_NODES * XP_STRIDE];
__device__ float4 g_acc[(size_t)N_NODES * 3];           // [num0..3][num4..7][num8,num9,den,-]

__device__ __forceinline__ void red_add_v4(float4* addr, float a, float b, float c, float d) {
    asm volatile("red.global.add.v4.f32 [%0], {%1, %2, %3, %4};"
                 :: "l"(addr), "f"(a), "f"(b), "f"(c), "f"(d)
                 : "memory");
}

__device__ __forceinline__ unsigned pk2(float a, float b) {
    __half2 h = __floats2half2_rn(a, b);
    return *reinterpret_cast<unsigned*>(&h);
}
__device__ __forceinline__ float2 up2(float fbits) {
    unsigned u = __float_as_uint(fbits);
    __half2 h = *reinterpret_cast<__half2*>(&u);
    return __half22float2(h);
}

// ---------------- kernel 0: zero accumulators ----------------
__global__ void k_zero() {
    size_t stride = (size_t)gridDim.x * blockDim.x;
    size_t total = (size_t)N_NODES * 3;
    for (size_t i = (size_t)blockIdx.x * blockDim.x + threadIdx.x; i < total; i += stride)
        g_acc[i] = make_float4(0.f, 0.f, 0.f, 0.f);
    if (blockIdx.x == 0) {
        if (threadIdx.x < F_IN) { g_sum[threadIdx.x] = 0.f; g_sq[threadIdx.x] = 0.f; }
        if (threadIdx.x == 32) g_wsum = 0.f;
    }
}

// ---------------- kernel 1: BN batch statistics ----------------
__global__ void k_bn_stats(const float* __restrict__ h) {
    __shared__ float red[8][2 * F_IN];
    int i = blockIdx.x * blockDim.x + threadIdx.x;
    int lane = threadIdx.x & 31;
    int warp = threadIdx.x >> 5;

    float v[F_IN];
#pragma unroll
    for (int f = 0; f < F_IN; f++) v[f] = 0.f;
    if (i < N_NODES) {
#pragma unroll
        for (int f = 0; f < F_IN; f++) v[f] = h[(size_t)i * F_IN + f];
    }
#pragma unroll
    for (int f = 0; f < F_IN; f++) {
        float sv = v[f];
        float qv = v[f] * v[f];
#pragma unroll
        for (int o = 16; o > 0; o >>= 1) {
            sv += __shfl_down_sync(0xffffffffu, sv, o);
            qv += __shfl_down_sync(0xffffffffu, qv, o);
        }
        if (lane == 0) { red[warp][f] = sv; red[warp][F_IN + f] = qv; }
    }
    __syncthreads();
    int j = threadIdx.x;
    if (j < 2 * F_IN) {
        float t = 0.f;
#pragma unroll
        for (int w = 0; w < 8; w++) t += red[w][j];
        if (j < F_IN) atomicAdd(&g_sum[j], t);
        else          atomicAdd(&g_sq[j - F_IN], t);
    }
}

// ---------------- kernel 2: BN + projection + attention terms ----------------
__global__ void __launch_bounds__(256) k_node_pre(const float* __restrict__ h,
                           const float* __restrict__ bn_w, const float* __restrict__ bn_b,
                           const float* __restrict__ W,
                           const float* __restrict__ att_src, const float* __restrict__ att_dst) {
    __shared__ float s_mu[F_IN], s_rs[F_IN], s_bw[F_IN], s_bb[F_IN];
    __shared__ float s_W[F_OUT * F_IN], s_as[F_OUT], s_ad[F_OUT];
    int t = threadIdx.x;
    if (t < F_IN) {
        float mu = g_sum[t] * (1.f / N_NODES);
        float var = g_sq[t] * (1.f / N_NODES) - mu * mu;
        s_mu[t] = mu;
        s_rs[t] = rsqrtf(var + BN_EPS);
        s_bw[t] = bn_w[t];
        s_bb[t] = bn_b[t];
    }
    if (t < F_OUT) { s_as[t] = att_src[t]; s_ad[t] = att_dst[t]; }
    for (int k = t; k < F_OUT * F_IN; k += blockDim.x) s_W[k] = W[k];
    __syncthreads();

    int i = blockIdx.x * blockDim.x + t;
    if (i >= N_NODES) return;

    float xn[F_IN];
#pragma unroll
    for (int f = 0; f < F_IN; f++)
        xn[f] = (h[(size_t)i * F_IN + f] - s_mu[f]) * s_rs[f] * s_bw[f] + s_bb[f];

    float as = 0.f, ad = 0.f;
    float a[F_OUT];
    float* xr = g_xp + (size_t)i * XP_STRIDE;
#pragma unroll
    for (int o = 0; o < F_OUT; o++) {
        float acc = 0.f;
#pragma unroll
        for (int k = 0; k < F_IN; k++) acc += xn[k] * s_W[o * F_IN + k];
        a[o] = acc;
        xr[o] = acc;
        as += acc * s_as[o];
        ad += acc * s_ad[o];
    }
    g_as_self[i] = as;
    g_ad[i] = ad;

    SrcPack p;
    p.a.x = __uint_as_float(pk2(a[0], a[1]));
    p.a.y = __uint_as_float(pk2(a[2], a[3]));
    p.a.z = __uint_as_float(pk2(a[4], a[5]));
    p.a.w = __uint_as_float(pk2(a[6], a[7]));
    p.b.x = __uint_as_float(pk2(a[8], a[9]));
    p.b.y = as;
    p.b.z = 0.f;
    p.b.w = 0.f;
    g_sx[i] = p;
}

// ---------------- kernel 3: edge pass, adjacent-pair vector loads ----------------
__global__ void __launch_bounds__(256) k_edges(const int* __restrict__ ei,
                                               const float* __restrict__ ew,
                                               const float* __restrict__ W_edge,
                                               const float* __restrict__ att_edge) {
    __shared__ float s_w[8];
    float c = 0.f;
#pragma unroll
    for (int f = 0; f < F_OUT; f++) c += W_edge[f] * att_edge[f];

    const int2*   eis = (const int2*)ei;                 // src pairs: ei[2i], ei[2i+1]
    const int2*   eid = (const int2*)(ei + N_EDGES);     // dst pairs
    const float2* ewp = (const float2*)ew;               // weight pairs

    float wacc = 0.f;
    int stride = gridDim.x * blockDim.x;
    for (int p = blockIdx.x * blockDim.x + threadIdx.x; p < EPAIRS; p += stride) {
        // -- one vector load per stream (3 instrs for 2 edges) --
        int2   sp = __ldcs(&eis[p]);
        int2   dp = __ldcs(&eid[p]);
        float2 wp = __ldcs(&ewp[p]);

        // -- batch independent random gathers for both edges --
        float4 p0a = g_sx[sp.x].a;
        float4 p0b = g_sx[sp.x].b;
        float4 p1a = g_sx[sp.y].a;
        float4 p1b = g_sx[sp.y].b;
        float  ad0 = g_ad[dp.x];
        float  ad1 = g_ad[dp.y];

        wacc += wp.x + wp.y;

        // -- edge 0 --
        {
            float l = p0b.y + ad0 + c * wp.x;
            l = fmaxf(l, 0.2f * l);
            float ex = __expf(l);
            float2 x01 = up2(p0a.x);
            float2 x23 = up2(p0a.y);
            float2 x45 = up2(p0a.z);
            float2 x67 = up2(p0a.w);
            float2 x89 = up2(p0b.x);
            float4* ab = &g_acc[(size_t)dp.x * 3];
            red_add_v4(&ab[0], ex * x01.x, ex * x01.y, ex * x23.x, ex * x23.y);
            red_add_v4(&ab[1], ex * x45.x, ex * x45.y, ex * x67.x, ex * x67.y);
            red_add_v4(&ab[2], ex * x89.x, ex * x89.y, ex, 0.f);
        }
        // -- edge 1 --
        {
            float l = p1b.y + ad1 + c * wp.y;
            l = fmaxf(l, 0.2f * l);
            float ex = __expf(l);
            float2 x01 = up2(p1a.x);
            float2 x23 = up2(p1a.y);
            float2 x45 = up2(p1a.z);
            float2 x67 = up2(p1a.w);
            float2 x89 = up2(p1b.x);
            float4* ab = &g_acc[(size_t)dp.y * 3];
            red_add_v4(&ab[0], ex * x01.x, ex * x01.y, ex * x23.x, ex * x23.y);
            red_add_v4(&ab[1], ex * x45.x, ex * x45.y, ex * x67.x, ex * x67.y);
            red_add_v4(&ab[2], ex * x89.x, ex * x89.y, ex, 0.f);
        }
    }

#pragma unroll
    for (int o = 16; o > 0; o >>= 1) wacc += __shfl_down_sync(0xffffffffu, wacc, o);
    if ((threadIdx.x & 31) == 0) s_w[threadIdx.x >> 5] = wacc;
    __syncthreads();
    if (threadIdx.x == 0) {
        float t = 0.f;
#pragma unroll
        for (int w = 0; w < 8; w++) t += s_w[w];
        atomicAdd(&g_wsum, t);
    }
}

// ---------------- kernel 4: self-loop + normalize + bias + MLP + outputs ----------------
__global__ void k_node_post(const float* __restrict__ W_edge, const float* __restrict__ att_edge,
                            const float* __restrict__ bias,
                            const float* __restrict__ fc1w, const float* __restrict__ fc1b,
                            const float* __restrict__ fc2w, const float* __restrict__ fc2b,
                            const float* __restrict__ fc3w, const float* __restrict__ fc3b,
                            float* __restrict__ out) {
    __shared__ float s1[F_OUT * F_OUT], s2[F_OUT * F_OUT], s3[F_OUT * F_OUT];
    __shared__ float b1[F_OUT], b2[F_OUT], b3[F_OUT], sb[F_OUT];
    int t = threadIdx.x;
    for (int k = t; k < F_OUT * F_OUT; k += blockDim.x) {
        s1[k] = fc1w[k]; s2[k] = fc2w[k]; s3[k] = fc3w[k];
    }
    if (t < F_OUT) { b1[t] = fc1b[t]; b2[t] = fc2b[t]; b3[t] = fc3b[t]; sb[t] = bias[t]; }
    __syncthreads();

    float c = 0.f;
#pragma unroll
    for (int f = 0; f < F_OUT; f++) c += W_edge[f] * att_edge[f];
    float wbar = g_wsum * (1.f / N_EDGES);

    int i = blockIdx.x * blockDim.x + t;
    if (i >= N_NODES) return;

    float l = g_as_self[i] + g_ad[i] + c * wbar;
    l = fmaxf(l, 0.2f * l);
    float exl = __expf(l);

    const float4* ab = &g_acc[(size_t)i * 3];
    float4 A0 = ab[0], A1 = ab[1], A2 = ab[2];
    const float* xr = g_xp + (size_t)i * XP_STRIDE;

    float num[F_OUT];
    num[0] = A0.x; num[1] = A0.y; num[2] = A0.z; num[3] = A0.w;
    num[4] = A1.x; num[5] = A1.y; num[6] = A1.z; num[7] = A1.w;
    num[8] = A2.x; num[9] = A2.y;
    float den = A2.z + exl;
    float rden = 1.f / den;

    float o[F_OUT];
#pragma unroll
    for (int f = 0; f < F_OUT; f++)
        o[f] = (num[f] + exl * xr[f]) * rden + sb[f];

    float* emb = out + (size_t)i * F_OUT;
#pragma unroll
    for (int f = 0; f < F_OUT; f++) emb[f] = fmaxf(o[f], 0.f);

    float y1[F_OUT], y2[F_OUT];
#pragma unroll
    for (int f = 0; f < F_OUT; f++) {
        float acc = b1[f];
#pragma unroll
        for (int k = 0; k < F_OUT; k++) acc += o[k] * s1[f * F_OUT + k];
        y1[f] = fmaxf(acc, 0.f);
    }
#pragma unroll
    for (int f = 0; f < F_OUT; f++) {
        float acc = b2[f];
#pragma unroll
        for (int k = 0; k < F_OUT; k++) acc += y1[k] * s2[f * F_OUT + k];
        y2[f] = fmaxf(acc, 0.f);
    }
    float* yo = out + (size_t)N_NODES * F_OUT + (size_t)i * F_OUT;
#pragma unroll
    for (int f = 0; f < F_OUT; f++) {
        float acc = b3[f];
#pragma unroll
        for (int k = 0; k < F_OUT; k++) acc += y2[k] * s3[f * F_OUT + k];
        yo[f] = acc;
    }
}

// ---------------- launch ----------------
extern "C" void kernel_launch(void* const* d_in, const int* in_sizes, int n_in,
                              void* d_out, int out_size) {
    const float* h        = (const float*)d_in[0];
    const int*   ei       = (const int*)d_in[1];
    const float* ew       = (const float*)d_in[2];
    const float* bn_w     = (const float*)d_in[3];
    const float* bn_b     = (const float*)d_in[4];
    const float* W        = (const float*)d_in[5];
    const float* att_src  = (const float*)d_in[6];
    const float* att_dst  = (const float*)d_in[7];
    const float* att_edge = (const float*)d_in[8];
    const float* W_edge   = (const float*)d_in[9];
    const float* bias     = (const float*)d_in[10];
    const float* fc1w     = (const float*)d_in[11];
    const float* fc1b     = (const float*)d_in[12];
    const float* fc2w     = (const float*)d_in[13];
    const float* fc2b     = (const float*)d_in[14];
    const float* fc3w     = (const float*)d_in[15];
    const float* fc3b     = (const float*)d_in[16];
    float* out = (float*)d_out;

    const int TPB = 256;
    const int node_blocks = (N_NODES + TPB - 1) / TPB;

    k_zero<<<1184, TPB>>>();
    k_bn_stats<<<node_blocks, TPB>>>(h);
    k_node_pre<<<node_blocks, TPB>>>(h, bn_w, bn_b, W, att_src, att_dst);
    k_edges<<<1184, TPB>>>(ei, ew, W_edge, att_edge);
    k_node_post<<<node_blocks, TPB>>>(W_edge, att_edge, bias,
                                      fc1w, fc1b, fc2w, fc2b, fc3w, fc3b, out);
}

// round 17
// speedup vs baseline: 2.7682x; 1.0260x over previous
#include <cuda_runtime.h>
#include <cuda_fp16.h>

#define N_NODES 200000
#define N_EDGES 6400000
#define F_IN 20
#define F_OUT 10
#define XP_STRIDE 12
#define BN_EPS 1e-5f

// ---------------- device scratch ----------------
__device__ float g_sum[F_IN];
__device__ float g_sq[F_IN];
__device__ float g_wsum;
__device__ float g_ad[N_NODES];

struct __align__(32) SrcPack { float4 a; float4 b; };   // 10xfp16 xp + fp32 a_s in ONE 32B sector
__device__ SrcPack g_sx[N_NODES];

__device__ float g_as_self[N_NODES];
__device__ __align__(16) float g_xp[(size_t)N_NODES * XP_STRIDE];
__device__ float4 g_acc[(size_t)N_NODES * 3];           // [num0..3][num4..7][num8,num9,den,-]

__device__ __forceinline__ void red_add_v4(float4* addr, float a, float b, float c, float d) {
    asm volatile("red.global.add.v4.f32 [%0], {%1, %2, %3, %4};"
                 :: "l"(addr), "f"(a), "f"(b), "f"(c), "f"(d)
                 : "memory");
}

__device__ __forceinline__ unsigned pk2(float a, float b) {
    __half2 h = __floats2half2_rn(a, b);
    return *reinterpret_cast<unsigned*>(&h);
}
__device__ __forceinline__ float2 up2(float fbits) {
    unsigned u = __float_as_uint(fbits);
    __half2 h = *reinterpret_cast<__half2*>(&u);
    return __half22float2(h);
}

// ---------------- kernel 0: zero scalars only (acc zeroed in bn_stats) ----------------
__global__ void k_zero() {
    int i = threadIdx.x;
    if (i < F_IN) { g_sum[i] = 0.f; g_sq[i] = 0.f; }
    if (i == 32) g_wsum = 0.f;
}

// ---------------- kernel 1: BN batch statistics + zero g_acc ----------------
__global__ void k_bn_stats(const float* __restrict__ h) {
    __shared__ float red[8][2 * F_IN];
    int i = blockIdx.x * blockDim.x + threadIdx.x;
    int lane = threadIdx.x & 31;
    int warp = threadIdx.x >> 5;

    // zero g_acc (independent work, completes before k_edges by stream order)
    {
        size_t stride = (size_t)gridDim.x * blockDim.x;
        size_t total = (size_t)N_NODES * 3;
        for (size_t k = (size_t)blockIdx.x * blockDim.x + threadIdx.x; k < total; k += stride)
            g_acc[k] = make_float4(0.f, 0.f, 0.f, 0.f);
    }

    float v[F_IN];
#pragma unroll
    for (int f = 0; f < F_IN; f++) v[f] = 0.f;
    if (i < N_NODES) {
#pragma unroll
        for (int f = 0; f < F_IN; f++) v[f] = h[(size_t)i * F_IN + f];
    }
#pragma unroll
    for (int f = 0; f < F_IN; f++) {
        float sv = v[f];
        float qv = v[f] * v[f];
#pragma unroll
        for (int o = 16; o > 0; o >>= 1) {
            sv += __shfl_down_sync(0xffffffffu, sv, o);
            qv += __shfl_down_sync(0xffffffffu, qv, o);
        }
        if (lane == 0) { red[warp][f] = sv; red[warp][F_IN + f] = qv; }
    }
    __syncthreads();
    int j = threadIdx.x;
    if (j < 2 * F_IN) {
        float t = 0.f;
#pragma unroll
        for (int w = 0; w < 8; w++) t += red[w][j];
        if (j < F_IN) atomicAdd(&g_sum[j], t);
        else          atomicAdd(&g_sq[j - F_IN], t);
    }
}

// ---------------- kernel 2: BN + projection + attention terms ----------------
__global__ void __launch_bounds__(256) k_node_pre(const float* __restrict__ h,
                           const float* __restrict__ bn_w, const float* __restrict__ bn_b,
                           const float* __restrict__ W,
                           const float* __restrict__ att_src, const float* __restrict__ att_dst) {
    __shared__ float s_mu[F_IN], s_rs[F_IN], s_bw[F_IN], s_bb[F_IN];
    __shared__ float s_W[F_OUT * F_IN], s_as[F_OUT], s_ad[F_OUT];
    int t = threadIdx.x;
    if (t < F_IN) {
        float mu = g_sum[t] * (1.f / N_NODES);
        float var = g_sq[t] * (1.f / N_NODES) - mu * mu;
        s_mu[t] = mu;
        s_rs[t] = rsqrtf(var + BN_EPS);
        s_bw[t] = bn_w[t];
        s_bb[t] = bn_b[t];
    }
    if (t < F_OUT) { s_as[t] = att_src[t]; s_ad[t] = att_dst[t]; }
    for (int k = t; k < F_OUT * F_IN; k += blockDim.x) s_W[k] = W[k];
    __syncthreads();

    int i = blockIdx.x * blockDim.x + t;
    if (i >= N_NODES) return;

    float xn[F_IN];
#pragma unroll
    for (int f = 0; f < F_IN; f++)
        xn[f] = (h[(size_t)i * F_IN + f] - s_mu[f]) * s_rs[f] * s_bw[f] + s_bb[f];

    float as = 0.f, ad = 0.f;
    float a[F_OUT];
    float* xr = g_xp + (size_t)i * XP_STRIDE;
#pragma unroll
    for (int o = 0; o < F_OUT; o++) {
        float acc = 0.f;
#pragma unroll
        for (int k = 0; k < F_IN; k++) acc += xn[k] * s_W[o * F_IN + k];
        a[o] = acc;
        xr[o] = acc;
        as += acc * s_as[o];
        ad += acc * s_ad[o];
    }
    g_as_self[i] = as;
    g_ad[i] = ad;

    SrcPack p;
    p.a.x = __uint_as_float(pk2(a[0], a[1]));
    p.a.y = __uint_as_float(pk2(a[2], a[3]));
    p.a.z = __uint_as_float(pk2(a[4], a[5]));
    p.a.w = __uint_as_float(pk2(a[6], a[7]));
    p.b.x = __uint_as_float(pk2(a[8], a[9]));
    p.b.y = as;
    p.b.z = 0.f;
    p.b.w = 0.f;
    g_sx[i] = p;
}

// ---------------- kernel 3: edge pass, pair-cooperative (2 lanes per edge) ----------------
__global__ void __launch_bounds__(256) k_edges(const int* __restrict__ ei,
                                               const float* __restrict__ ew,
                                               const float* __restrict__ W_edge,
                                               const float* __restrict__ att_edge) {
    __shared__ float s_w[8];
    float c = 0.f;
#pragma unroll
    for (int f = 0; f < F_OUT; f++) c += W_edge[f] * att_edge[f];

    int lane   = threadIdx.x & 31;
    int pairId = lane >> 1;          // 0..15: which edge within the warp's batch of 16
    int half   = lane & 1;           // 0: bytes [0,16) / n0..n3;  1: bytes [16,32) / n4..n7

    int warpId       = (blockIdx.x * blockDim.x + threadIdx.x) >> 5;
    int warpsInGrid  = (gridDim.x * blockDim.x) >> 5;

    float wacc = 0.f;
    for (int base = warpId * 16; base < N_EDGES; base += warpsInGrid * 16) {
        int e = base + pairId;                        // N_EDGES % 16 == 0, always in range
        int   s = ei[e];
        int   d = ei[N_EDGES + e];
        float w = ew[e];

        // cooperative 32B gather: pair's two lanes hit the same sector -> 1 wavefront
        const float4* sxp = (const float4*)&g_sx[s];
        float4 mine = __ldg(&sxp[half]);
        float  ad   = g_ad[d];                        // both lanes same addr -> broadcast

        // exchange halves so both lanes hold the full pack
        float4 other;
        other.x = __shfl_xor_sync(0xffffffffu, mine.x, 1);
        other.y = __shfl_xor_sync(0xffffffffu, mine.y, 1);
        other.z = __shfl_xor_sync(0xffffffffu, mine.z, 1);
        other.w = __shfl_xor_sync(0xffffffffu, mine.w, 1);
        float4 pa = half ? other : mine;              // h2 x01,x23,x45,x67
        float4 pb = half ? mine  : other;             // h2 x89 | a_s | pad | pad

        float l = pb.y + ad + c * w;
        l = fmaxf(l, 0.2f * l);                       // leaky_relu(l, 0.2)
        float ex = __expf(l);

        // RED 1 (split across the pair, same 32B sector -> merged wavefront):
        //   even lane: n0..n3 at +0 ; odd lane: n4..n7 at +16
        float2 xA = up2(half ? pa.z : pa.x);
        float2 xB = up2(half ? pa.w : pa.y);
        char* accb = (char*)&g_acc[(size_t)d * 3];
        red_add_v4((float4*)(accb + (half << 4)),
                   ex * xA.x, ex * xA.y, ex * xB.x, ex * xB.y);

        // RED 2 (even lanes only): n8, n9, den at +32
        if (!half) {
            float2 x89 = up2(pb.x);
            red_add_v4((float4*)(accb + 32), ex * x89.x, ex * x89.y, ex, 0.f);
            wacc += w;                                 // count each edge once
        }
    }

#pragma unroll
    for (int o = 16; o > 0; o >>= 1) wacc += __shfl_down_sync(0xffffffffu, wacc, o);
    if ((threadIdx.x & 31) == 0) s_w[threadIdx.x >> 5] = wacc;
    __syncthreads();
    if (threadIdx.x == 0) {
        float t = 0.f;
#pragma unroll
        for (int w = 0; w < 8; w++) t += s_w[w];
        atomicAdd(&g_wsum, t);
    }
}

// ---------------- kernel 4: self-loop + normalize + bias + MLP + outputs ----------------
__global__ void k_node_post(const float* __restrict__ W_edge, const float* __restrict__ att_edge,
                            const float* __restrict__ bias,
                            const float* __restrict__ fc1w, const float* __restrict__ fc1b,
                            const float* __restrict__ fc2w, const float* __restrict__ fc2b,
                            const float* __restrict__ fc3w, const float* __restrict__ fc3b,
                            float* __restrict__ out) {
    __shared__ float s1[F_OUT * F_OUT], s2[F_OUT * F_OUT], s3[F_OUT * F_OUT];
    __shared__ float b1[F_OUT], b2[F_OUT], b3[F_OUT], sb[F_OUT];
    int t = threadIdx.x;
    for (int k = t; k < F_OUT * F_OUT; k += blockDim.x) {
        s1[k] = fc1w[k]; s2[k] = fc2w[k]; s3[k] = fc3w[k];
    }
    if (t < F_OUT) { b1[t] = fc1b[t]; b2[t] = fc2b[t]; b3[t] = fc3b[t]; sb[t] = bias[t]; }
    __syncthreads();

    float c = 0.f;
#pragma unroll
    for (int f = 0; f < F_OUT; f++) c += W_edge[f] * att_edge[f];
    float wbar = g_wsum * (1.f / N_EDGES);

    int i = blockIdx.x * blockDim.x + t;
    if (i >= N_NODES) return;

    float l = g_as_self[i] + g_ad[i] + c * wbar;
    l = fmaxf(l, 0.2f * l);
    float exl = __expf(l);

    const float4* ab = &g_acc[(size_t)i * 3];
    float4 A0 = ab[0], A1 = ab[1], A2 = ab[2];
    const float* xr = g_xp + (size_t)i * XP_STRIDE;

    float num[F_OUT];
    num[0] = A0.x; num[1] = A0.y; num[2] = A0.z; num[3] = A0.w;
    num[4] = A1.x; num[5] = A1.y; num[6] = A1.z; num[7] = A1.w;
    num[8] = A2.x; num[9] = A2.y;
    float den = A2.z + exl;
    float rden = 1.f / den;

    float o[F_OUT];
#pragma unroll
    for (int f = 0; f < F_OUT; f++)
        o[f] = (num[f] + exl * xr[f]) * rden + sb[f];

    float* emb = out + (size_t)i * F_OUT;
#pragma unroll
    for (int f = 0; f < F_OUT; f++) emb[f] = fmaxf(o[f], 0.f);

    float y1[F_OUT], y2[F_OUT];
#pragma unroll
    for (int f = 0; f < F_OUT; f++) {
        float acc = b1[f];
#pragma unroll
        for (int k = 0; k < F_OUT; k++) acc += o[k] * s1[f * F_OUT + k];
        y1[f] = fmaxf(acc, 0.f);
    }
#pragma unroll
    for (int f = 0; f < F_OUT; f++) {
        float acc = b2[f];
#pragma unroll
        for (int k = 0; k < F_OUT; k++) acc += y1[k] * s2[f * F_OUT + k];
        y2[f] = fmaxf(acc, 0.f);
    }
    float* yo = out + (size_t)N_NODES * F_OUT + (size_t)i * F_OUT;
#pragma unroll
    for (int f = 0; f < F_OUT; f++) {
        float acc = b3[f];
#pragma unroll
        for (int k = 0; k < F_OUT; k++) acc += y2[k] * s3[f * F_OUT + k];
        yo[f] = acc;
    }
}

// ---------------- launch ----------------
extern "C" void kernel_launch(void* const* d_in, const int* in_sizes, int n_in,
                              void* d_out, int out_size) {
    const float* h        = (const float*)d_in[0];
    const int*   ei       = (const int*)d_in[1];
    const float* ew       = (const float*)d_in[2];
    const float* bn_w     = (const float*)d_in[3];
    const float* bn_b     = (const float*)d_in[4];
    const float* W        = (const float*)d_in[5];
    const float* att_src  = (const float*)d_in[6];
    const float* att_dst  = (const float*)d_in[7];
    const float* att_edge = (const float*)d_in[8];
    const float* W_edge   = (const float*)d_in[9];
    const float* bias     = (const float*)d_in[10];
    const float* fc1w     = (const float*)d_in[11];
    const float* fc1b     = (const float*)d_in[12];
    const float* fc2w     = (const float*)d_in[13];
    const float* fc2b     = (const float*)d_in[14];
    const float* fc3w     = (const float*)d_in[15];
    const float* fc3b     = (const float*)d_in[16];
    float* out = (float*)d_out;

    const int TPB = 256;
    const int node_blocks = (N_NODES + TPB - 1) / TPB;

    k_zero<<<1, 64>>>();
    k_bn_stats<<<node_blocks, TPB>>>(h);
    k_node_pre<<<node_blocks, TPB>>>(h, bn_w, bn_b, W, att_src, att_dst);
    k_edges<<<1184, TPB>>>(ei, ew, W_edge, att_edge);
    k_node_post<<<node_blocks, TPB>>>(W_edge, att_edge, bias,
                                      fc1w, fc1b, fc2w, fc2b, fc3w, fc3b, out);
}